// round 1
// baseline (speedup 1.0000x reference)
#include <cuda_runtime.h>
#include <cstdint>

// Problem constants
#define T_STEPS 512
#define B_TOT   1024
#define IN_DIM  128
#define H_DIM   256
#define OUT_DIM 4
#define K_DIM   384          // IN + H
#define K4      96           // K_DIM / 4
#define BB      8            // batch rows per block
#define NBLOCKS (B_TOT / BB) // 128
#define NTHREADS 256
#define WSTR4   99           // padded row stride in float4 (396 floats)

#define HS0_OFF ((size_t)T_STEPS * B_TOT * OUT_DIM)  // 2,097,152

// Shared memory layout (bytes):
//   sW   : 64 * 99 f4  = 101376
//   sC   :  8 * 99 f4  =  12672   (combined [x | h], 384 used cols)
//   sWo  :  4 * 96 f4  =   6144
//   sHn  : 2048 f      =   8192
//   sBh  : 256 f       =   1024
//   sAct : 1024 f      =   4096
//   sOut : 32 f        =    128
//   sBo  : 4 f         =     16
//   sQ   : 8 int       =     32
#define SMEM_BYTES 133680

typedef unsigned long long u64;

__device__ __forceinline__ void ffma2(u64& d, u64 a, u64 b) {
    // packed f32x2 FMA: 2 fp32 FMAs per instruction (rt_SMSP=2 but 2 lanes)
    asm("fma.rn.f32x2 %0, %1, %2, %0;" : "+l"(d) : "l"(a), "l"(b));
}
__device__ __forceinline__ float hsum2(u64 a, u64 b) {
    float x0, x1, y0, y1;
    asm("mov.b64 {%0,%1}, %2;" : "=f"(x0), "=f"(x1) : "l"(a));
    asm("mov.b64 {%0,%1}, %2;" : "=f"(y0), "=f"(y1) : "l"(b));
    return (x0 + x1) + (y0 + y1);
}

extern __shared__ float4 smem_dyn[];

__global__ void __launch_bounds__(NTHREADS, 1)
rnn_persistent_kernel(const float* __restrict__ inp,
                      const float* __restrict__ hidden,
                      const float* __restrict__ W_i2h,
                      const float* __restrict__ b_i2h,
                      const float* __restrict__ W_i2o,
                      const float* __restrict__ b_i2o,
                      const float* __restrict__ actions,
                      float* __restrict__ out)
{
    float4* sW  = smem_dyn;                 // 64 * WSTR4
    float4* sC  = sW  + 64 * WSTR4;         // BB * WSTR4
    float4* sWo = sC  + BB * WSTR4;         // 4 * 96
    float*  sHn = (float*)(sWo + 4 * 96);   // BB * 256
    float*  sBh = sHn + BB * 256;           // 256
    float*  sAct = sBh + 256;               // 1024
    float*  sOut = sAct + 1024;             // 32
    float*  sBo  = sOut + 32;               // 4
    int*    sQ   = (int*)(sBo + 4);         // 8

    const int tid = threadIdx.x;
    const int bs  = blockIdx.x * BB;        // first batch row of this block

    // ---- one-time loads -------------------------------------------------
    const float4* Wo4 = (const float4*)W_i2o;
    for (int i = tid; i < 4 * 96; i += NTHREADS) sWo[i] = Wo4[i];
    if (tid < 256) sBh[tid] = b_i2h[tid];
    if (tid < 4)   sBo[tid] = b_i2o[tid];
    for (int i = tid; i < 4 * 256; i += NTHREADS) sAct[i] = actions[i];
    {
        const float4* h4 = (const float4*)hidden;
        for (int i = tid; i < BB * 64; i += NTHREADS) {
            int r = i >> 6, jj = i & 63;
            sC[r * WSTR4 + 32 + jj] = h4[(size_t)(bs + r) * 64 + jj];
        }
    }
    __syncthreads();

    const float4* Wh4 = (const float4*)W_i2h;   // [256][96] float4

    const int jl = tid & 63;          // tile-local output column
    const int rg = tid >> 6;          // 0..3
    const int r0 = rg * 2;
    const int r1 = r0 + 1;
    const ulonglong2* cA2 = (const ulonglong2*)(sC + (size_t)r0 * WSTR4);
    const ulonglong2* cB2 = (const ulonglong2*)(sC + (size_t)r1 * WSTR4);
    const ulonglong2* w2  = (const ulonglong2*)(sW + (size_t)jl * WSTR4);

    for (int t = 0; t < T_STEPS; ++t) {
        // ---- S0: load x slice [BB,128] into combined --------------------
        {
            const float4* x4 = (const float4*)inp + ((size_t)t * B_TOT + bs) * 32;
            int r = tid >> 5, kk = tid & 31;
            sC[r * WSTR4 + kk] = x4[r * 32 + kk];
        }
        __syncthreads();

        // ---- S1: warp0 = output logits + argmax; warps 1..7 = W tile 0 --
        if (tid < 32) {
            int r = tid >> 2, o = tid & 3;
            const float4* c = sC + (size_t)r * WSTR4;
            const float4* w = sWo + (size_t)o * 96;
            float a0 = 0.f, a1 = 0.f;
            #pragma unroll 8
            for (int kk = 0; kk < 96; kk += 2) {
                float4 c0 = c[kk],   w0 = w[kk];
                a0 += c0.x * w0.x + c0.y * w0.y + c0.z * w0.z + c0.w * w0.w;
                float4 c1 = c[kk+1], w1 = w[kk+1];
                a1 += c1.x * w1.x + c1.y * w1.y + c1.z * w1.z + c1.w * w1.w;
            }
            float val = a0 + a1 + sBo[o];
            sOut[tid] = val;
            __syncwarp();
            if (o == 0) {
                float best = sOut[r * 4];
                int   q    = 0;
                #pragma unroll
                for (int oo = 1; oo < 4; ++oo) {
                    float v = sOut[r * 4 + oo];
                    if (v > best) { best = v; q = oo; }
                }
                sQ[r] = q;
            }
            // coalesced logit write: out[(t*B + bs + r)*4 + o]
            out[((size_t)t * B_TOT + bs) * 4 + tid] = sOut[tid];
        } else {
            // load W tile 0 (rows 0..63) with 224 threads
            for (int i = tid - 32; i < 64 * 96; i += NTHREADS - 32) {
                int row = i / 96, kk = i - row * 96;
                sW[row * WSTR4 + kk] = Wh4[i];
            }
        }

        // ---- S2: 4 N-tiles of the hidden GEMM ---------------------------
        #pragma unroll 1
        for (int tt = 0; tt < 4; ++tt) {
            __syncthreads();    // tile ready (and sQ ready for tt==0)

            u64 aLo = 0ull, aHi = 0ull, bLo = 0ull, bHi = 0ull;
            #pragma unroll 4
            for (int kk = 0; kk < K4; ++kk) {
                ulonglong2 wv = w2[kk];
                ulonglong2 av = cA2[kk];
                ulonglong2 bv = cB2[kk];
                ffma2(aLo, wv.x, av.x);
                ffma2(aHi, wv.y, av.y);
                ffma2(bLo, wv.x, bv.x);
                ffma2(bHi, wv.y, bv.y);
            }
            int j = tt * 64 + jl;
            float zA = hsum2(aLo, aHi) + sBh[j];
            float zB = hsum2(bLo, bHi) + sBh[j];
            float hA = tanhf(zA);
            float hB = tanhf(zB);
            sHn[r0 * 256 + j] = hA * (1.0f + sAct[sQ[r0] * 256 + j]);
            sHn[r1 * 256 + j] = hB * (1.0f + sAct[sQ[r1] * 256 + j]);
            if (t == 0) {
                // hs[0] = pre-gating tanh output of step 0
                out[HS0_OFF + (size_t)(bs + r0) * 256 + j] = hA;
                out[HS0_OFF + (size_t)(bs + r1) * 256 + j] = hB;
            }

            __syncthreads();    // all reads of sW / sC complete
            if (tt < 3) {
                int base = (tt + 1) * 64 * 96;
                for (int i = tid; i < 64 * 96; i += NTHREADS) {
                    int row = i / 96, kk = i - row * 96;
                    sW[row * WSTR4 + kk] = Wh4[base + i];
                }
            }
        }

        // ---- S3: commit gated hidden state into combined ----------------
        {
            const float4* hn4 = (const float4*)sHn;
            for (int i = tid; i < BB * 64; i += NTHREADS) {
                int r = i >> 6, jj = i & 63;
                sC[r * WSTR4 + 32 + jj] = hn4[i];
            }
        }
        __syncthreads();
    }
}

extern "C" void kernel_launch(void* const* d_in, const int* in_sizes, int n_in,
                              void* d_out, int out_size)
{
    const float* inp     = (const float*)d_in[0];
    const float* hidden  = (const float*)d_in[1];
    const float* W_i2h   = (const float*)d_in[2];
    const float* b_i2h   = (const float*)d_in[3];
    const float* W_i2o   = (const float*)d_in[4];
    const float* b_i2o   = (const float*)d_in[5];
    const float* actions = (const float*)d_in[6];
    float* out = (float*)d_out;

    cudaFuncSetAttribute(rnn_persistent_kernel,
                         cudaFuncAttributeMaxDynamicSharedMemorySize, SMEM_BYTES);

    rnn_persistent_kernel<<<NBLOCKS, NTHREADS, SMEM_BYTES>>>(
        inp, hidden, W_i2h, b_i2h, W_i2o, b_i2o, actions, out);
}

// round 2
// speedup vs baseline: 2.2443x; 2.2443x over previous
#include <cuda_runtime.h>
#include <cstdint>

// Problem constants
#define T_STEPS 512
#define B_TOT   1024
#define IN_DIM  128
#define H_DIM   256
#define OUT_DIM 4
#define BB      8            // batch rows per block (sequential kernel)
#define NBLK_C  (B_TOT / BB) // 128
#define NTHR_C  288          // 8 GEMM warps + 1 logits warp

#define HS0_OFF ((size_t)T_STEPS * B_TOT * OUT_DIM)  // 2,097,152

typedef unsigned long long u64;

// ---------------- scratch (no cudaMalloc allowed) -------------------------
__device__ float g_xproj[(size_t)T_STEPS * B_TOT * H_DIM];   // 512 MiB, x@Wx^T + b_i2h
__device__ float g_outx [(size_t)T_STEPS * B_TOT * OUT_DIM]; // 8 MiB,   x@Wox^T + b_i2o

// ---------------- helpers --------------------------------------------------
__device__ __forceinline__ void ffma2(u64& d, u64 a, u64 b) {
    asm("fma.rn.f32x2 %0, %1, %2, %0;" : "+l"(d) : "l"(a), "l"(b));
}
__device__ __forceinline__ u64 pack2(float a, float b) {
    u64 r; asm("mov.b64 %0, {%1, %2};" : "=l"(r) : "f"(a), "f"(b)); return r;
}
__device__ __forceinline__ float hsum2(u64 a) {
    float x, y; asm("mov.b64 {%0,%1}, %2;" : "=f"(x), "=f"(y) : "l"(a));
    return x + y;
}

// ===========================================================================
// Kernel A: X_proj[t,b,:] = inp[t,b,:] @ Wx^T + b_i2h      (M=524288,N=256,K=128)
// Tile: 128 rows x 256 cols per CTA. Thread tile 8x16, fp32 packed FFMA2.
// ===========================================================================
#define A_SXSTR 132   // padded float stride of x tile rows
extern __shared__ float smemA[];

__global__ void __launch_bounds__(256, 1)
xproj_kernel(const float* __restrict__ inp,
             const float* __restrict__ W_i2h,
             const float* __restrict__ b_i2h)
{
    float* sX  = smemA;                 // 128 * 132 floats = 67584 f
    float* sWt = smemA + 128 * A_SXSTR; // [k][j] 128*256   = 32768 f  (transposed W)

    const int tid = threadIdx.x;
    const int m0  = blockIdx.x * 128;

    // fill x tile (coalesced float4)
    const float4* in4 = (const float4*)inp;
    #pragma unroll
    for (int it = 0; it < 16; ++it) {
        int idx = tid + it * 256;
        int row = idx >> 5, k4 = idx & 31;
        *(float4*)&sX[row * A_SXSTR + k4 * 4] = in4[((size_t)(m0 + row)) * 32 + k4];
    }
    // fill transposed W (x-part = first 32 float4 of each 96-float4 row)
    const float4* w4 = (const float4*)W_i2h;
    #pragma unroll
    for (int k4 = 0; k4 < 32; ++k4) {
        float4 v = w4[(size_t)tid * 96 + k4];
        sWt[(k4 * 4 + 0) * 256 + tid] = v.x;
        sWt[(k4 * 4 + 1) * 256 + tid] = v.y;
        sWt[(k4 * 4 + 2) * 256 + tid] = v.z;
        sWt[(k4 * 4 + 3) * 256 + tid] = v.w;
    }
    __syncthreads();

    const int ty = tid >> 4, tx = tid & 15;
    const float* xs = sX + ty * 8 * A_SXSTR;
    const float* ws = sWt + tx * 16;

    // bias init (packed)
    u64 acc[8][8];
    {
        const float* b = b_i2h + tx * 16;
        u64 bp[8];
        #pragma unroll
        for (int jj = 0; jj < 8; ++jj) bp[jj] = pack2(b[2 * jj], b[2 * jj + 1]);
        #pragma unroll
        for (int i = 0; i < 8; ++i)
            #pragma unroll
            for (int jj = 0; jj < 8; ++jj) acc[i][jj] = bp[jj];
    }

    #pragma unroll 2
    for (int k = 0; k < 128; ++k) {
        u64 wv[8];
        {
            const ulonglong2* wp = (const ulonglong2*)(ws + (size_t)k * 256);
            ulonglong2 w0 = wp[0], w1 = wp[1], w2 = wp[2], w3 = wp[3];
            wv[0] = w0.x; wv[1] = w0.y; wv[2] = w1.x; wv[3] = w1.y;
            wv[4] = w2.x; wv[5] = w2.y; wv[6] = w3.x; wv[7] = w3.y;
        }
        #pragma unroll
        for (int i = 0; i < 8; ++i) {
            float av = xs[i * A_SXSTR + k];
            u64 aa = pack2(av, av);
            #pragma unroll
            for (int jj = 0; jj < 8; ++jj) ffma2(acc[i][jj], wv[jj], aa);
        }
    }

    // write out
    float* xp = g_xproj;
    #pragma unroll
    for (int i = 0; i < 8; ++i) {
        size_t base = ((size_t)(m0 + ty * 8 + i)) * 256 + tx * 16;
        #pragma unroll
        for (int q = 0; q < 4; ++q) {
            float lo0, hi0, lo1, hi1;
            asm("mov.b64 {%0,%1}, %2;" : "=f"(lo0), "=f"(hi0) : "l"(acc[i][2 * q]));
            asm("mov.b64 {%0,%1}, %2;" : "=f"(lo1), "=f"(hi1) : "l"(acc[i][2 * q + 1]));
            *(float4*)&xp[base + q * 4] = make_float4(lo0, hi0, lo1, hi1);
        }
    }
}

// ===========================================================================
// Kernel B: OutX[t,b,o] = inp[t,b,:] @ Wo_x^T + b_i2o   (memory-bound)
// ===========================================================================
__global__ void __launch_bounds__(256, 4)
outx_kernel(const float* __restrict__ inp,
            const float* __restrict__ W_i2o,
            const float* __restrict__ b_i2o)
{
    __shared__ float sW[4 * 128];   // x-part of W_i2o
    __shared__ float sB[4];
    const int tid = threadIdx.x;
    if (tid < 128) {
        #pragma unroll
        for (int o = 0; o < 4; ++o) sW[o * 128 + tid] = W_i2o[o * 384 + tid];
    }
    if (tid < 4) sB[tid] = b_i2o[tid];
    __syncthreads();

    size_t row = (size_t)blockIdx.x * 256 + tid;
    const float4* x4 = (const float4*)inp + row * 32;
    float a0 = sB[0], a1 = sB[1], a2 = sB[2], a3 = sB[3];
    const float4* w0 = (const float4*)sW;
    const float4* w1 = (const float4*)(sW + 128);
    const float4* w2 = (const float4*)(sW + 256);
    const float4* w3 = (const float4*)(sW + 384);
    #pragma unroll 8
    for (int k4 = 0; k4 < 32; ++k4) {
        float4 x = x4[k4];
        float4 v;
        v = w0[k4]; a0 += x.x * v.x + x.y * v.y + x.z * v.z + x.w * v.w;
        v = w1[k4]; a1 += x.x * v.x + x.y * v.y + x.z * v.z + x.w * v.w;
        v = w2[k4]; a2 += x.x * v.x + x.y * v.y + x.z * v.z + x.w * v.w;
        v = w3[k4]; a3 += x.x * v.x + x.y * v.y + x.z * v.z + x.w * v.w;
    }
    *(float4*)&g_outx[row * 4] = make_float4(a0, a1, a2, a3);
}

// ===========================================================================
// Kernel C: sequential recurrence. 128 CTAs x 8 batch rows, 512 steps.
// W_h resident: k4 0..15 in regs, k4 16..63 in smem (padded stride 49 f4).
// Warps 0..7: h GEMM (col = tid, 8 rows). Warp 8: logits + argmax.
// ===========================================================================
#define WPAD4 49
// smem floats: sW 256*49*4=50176f, sH 2048f, sWo 4*260=1040f, sAct 1024f,
//              sOut 32f, sQ 8i
#define C_SW_F   (256 * WPAD4 * 4)
#define C_SH_F   (C_SW_F)                 // offset of sH
#define C_SWO_F  (C_SH_F + BB * 256)
#define C_SACT_F (C_SWO_F + 4 * 260)
#define C_SOUT_F (C_SACT_F + 4 * 256)
#define C_SQ_F   (C_SOUT_F + 32)
#define C_SMEM_BYTES ((C_SQ_F + 8) * 4)   // 217,472 B < 227 KB

extern __shared__ float smemC[];

__global__ void __launch_bounds__(NTHR_C, 1)
rnn_seq_kernel(const float* __restrict__ hidden,
               const float* __restrict__ W_i2h,
               const float* __restrict__ W_i2o,
               const float* __restrict__ actions,
               float* __restrict__ out)
{
    float* sW   = smemC;
    float* sH   = smemC + C_SH_F;
    float* sWo  = smemC + C_SWO_F;
    float* sAct = smemC + C_SACT_F;
    float* sOut = smemC + C_SOUT_F;
    int*   sQ   = (int*)(smemC + C_SQ_F);

    const int tid = threadIdx.x;
    const int bs  = blockIdx.x * BB;

    // ---- one-time fills ---------------------------------------------------
    const float4* Wh4 = (const float4*)W_i2h;   // [256][96] f4 per row
    if (tid < 256) {
        // smem W part: k4 16..63 -> row f4 indices 48..95
        #pragma unroll 8
        for (int k4 = 16; k4 < 64; ++k4)
            ((float4*)sW)[tid * WPAD4 + (k4 - 16)] = Wh4[(size_t)tid * 96 + 32 + k4];
        // initial hidden
        #pragma unroll
        for (int r = 0; r < BB; ++r)
            sH[r * 256 + tid] = hidden[(size_t)(bs + r) * 256 + tid];
        // W_i2o h-part, padded stride 260
        #pragma unroll
        for (int i = tid; i < 4 * 256; i += 256)
            sWo[(i >> 8) * 260 + (i & 255)] = W_i2o[(i >> 8) * 384 + 128 + (i & 255)];
        // actions
        #pragma unroll
        for (int i = tid; i < 4 * 256; i += 256) sAct[i] = actions[i];
    }

    // ---- register-resident W part (k4 0..15) -------------------------------
    u64 wlo[16], whi[16];
    if (tid < 256) {
        #pragma unroll
        for (int k4 = 0; k4 < 16; ++k4) {
            float4 v = Wh4[(size_t)tid * 96 + 32 + k4];
            wlo[k4] = pack2(v.x, v.y);
            whi[k4] = pack2(v.z, v.w);
        }
    }
    __syncthreads();

    const int col = tid;                       // GEMM threads: 0..255
    const ulonglong2* sW2 = (const ulonglong2*)sW + (size_t)col * WPAD4;

    // X_proj prefetch for t=0
    float xp[BB];
    if (tid < 256) {
        #pragma unroll
        for (int r = 0; r < BB; ++r)
            xp[r] = g_xproj[((size_t)(0 * B_TOT) + bs + r) * 256 + col];
    }
    float oxCur = 0.f;
    const int lane = tid - 256;                // logits warp lane (valid when >=0)
    if (tid >= 256) oxCur = g_outx[((size_t)0 * B_TOT + bs) * 4 + lane];

    for (int t = 0; t < T_STEPS; ++t) {
        const int tn = (t + 1 < T_STEPS) ? (t + 1) : t;

        if (tid < 256) {
            // ---- accumulators init + prefetch next X_proj ------------------
            u64 aL[BB], aH[BB];
            #pragma unroll
            for (int r = 0; r < BB; ++r) { aL[r] = pack2(xp[r], 0.f); aH[r] = 0ull; }
            #pragma unroll
            for (int r = 0; r < BB; ++r)
                xp[r] = g_xproj[((size_t)tn * B_TOT + bs + r) * 256 + col];

            // ---- K part 1: register W --------------------------------------
            #pragma unroll
            for (int k4 = 0; k4 < 16; ++k4) {
                #pragma unroll
                for (int r = 0; r < BB; ++r) {
                    ulonglong2 c = *(const ulonglong2*)(sH + r * 256 + k4 * 4);
                    ffma2(aL[r], wlo[k4], c.x);
                    ffma2(aH[r], whi[k4], c.y);
                }
            }
            // ---- K part 2: smem W ------------------------------------------
            #pragma unroll 4
            for (int k4 = 16; k4 < 64; ++k4) {
                ulonglong2 w = sW2[k4 - 16];
                #pragma unroll
                for (int r = 0; r < BB; ++r) {
                    ulonglong2 c = *(const ulonglong2*)(sH + r * 256 + k4 * 4);
                    ffma2(aL[r], w.x, c.x);
                    ffma2(aH[r], w.y, c.y);
                }
            }

            __syncthreads();   // #2: sQ ready, all sH reads done

            // ---- epilogue: tanh, gate, commit new h ------------------------
            #pragma unroll
            for (int r = 0; r < BB; ++r) {
                float z = hsum2(aL[r]) + hsum2(aH[r]);
                float hA = tanhf(z);
                if (t == 0)
                    out[HS0_OFF + (size_t)(bs + r) * 256 + col] = hA;
                float g = hA * (1.0f + sAct[sQ[r] * 256 + col]);
                sH[r * 256 + col] = g;
            }
        } else if (lane < 32) {
            // ---- logits warp -----------------------------------------------
            const int r = lane >> 2, o = lane & 3;
            float acc = oxCur;
            const float4* hp = (const float4*)(sH + r * 256);
            const float4* wp = (const float4*)(sWo + o * 260);
            #pragma unroll 8
            for (int k4 = 0; k4 < 64; ++k4) {
                float4 h4 = hp[k4], w4 = wp[k4];
                acc += h4.x * w4.x + h4.y * w4.y + h4.z * w4.z + h4.w * w4.w;
            }
            sOut[lane] = acc;
            __syncwarp();
            if (o == 0) {
                float best = sOut[r * 4]; int q = 0;
                #pragma unroll
                for (int oo = 1; oo < 4; ++oo) {
                    float v = sOut[r * 4 + oo];
                    if (v > best) { best = v; q = oo; }
                }
                sQ[r] = q;
            }
            out[((size_t)t * B_TOT + bs) * 4 + lane] = acc;
            // prefetch next OutX
            oxCur = g_outx[((size_t)tn * B_TOT + bs) * 4 + lane];

            __syncthreads();   // #2
        } else {
            __syncthreads();   // #2
        }

        __syncthreads();       // #1: new h visible to everyone
    }
}

// ===========================================================================
extern "C" void kernel_launch(void* const* d_in, const int* in_sizes, int n_in,
                              void* d_out, int out_size)
{
    const float* inp     = (const float*)d_in[0];
    const float* hidden  = (const float*)d_in[1];
    const float* W_i2h   = (const float*)d_in[2];
    const float* b_i2h   = (const float*)d_in[3];
    const float* W_i2o   = (const float*)d_in[4];
    const float* b_i2o   = (const float*)d_in[5];
    const float* actions = (const float*)d_in[6];
    float* out = (float*)d_out;

    const int smemA = (128 * A_SXSTR + 128 * 256) * 4;   // 198,656 B
    cudaFuncSetAttribute(xproj_kernel,
                         cudaFuncAttributeMaxDynamicSharedMemorySize, smemA);
    cudaFuncSetAttribute(rnn_seq_kernel,
                         cudaFuncAttributeMaxDynamicSharedMemorySize, C_SMEM_BYTES);

    // A: X_proj (parallel over all T*B rows)
    xproj_kernel<<<(T_STEPS * B_TOT) / 128, 256, smemA>>>(inp, W_i2h, b_i2h);
    // B: OutX
    outx_kernel<<<(T_STEPS * B_TOT) / 256, 256>>>(inp, W_i2o, b_i2o);
    // C: sequential recurrence
    rnn_seq_kernel<<<NBLK_C, NTHR_C, C_SMEM_BYTES>>>(hidden, W_i2h, W_i2o,
                                                     actions, out);
}